// round 16
// baseline (speedup 1.0000x reference)
#include <cuda_runtime.h>
#include <cuda_fp16.h>
#include <math.h>
#include <stdint.h>

#define T_LEN 128
#define NB    1024
#define D_IN  128
#define H_DIM 512
#define G_DIM 1536
#define ROWS  (T_LEN * NB)     // 131072

// ---------------- scratch (__device__ globals) ------------------------------
__device__ __half g_oT[1024][2][8192];      // obs fp16 tiles [rt][kt] 128x64, SW128
__device__ __half g_W1T[4][2][8192];        // W1 tiles [nt][kt] 128x64
__device__ __half g_xT[1024][8][8192];      // x fp16 tiles [rt][kt] 128x64, SW128
__device__ __half g_WihT[16][8][6144];      // W_ih [jc][kt] 96x64 gate-triple
__device__ __half g_WhhT[16][8][6144];      // W_hh [jc][kt] 96x64 gate-triple
__device__ __half g_hT[2][8][8][8192];      // h fp16 tiles ping-pong [mt][kt] 128x64
__device__ unsigned g_hrdy[8][8];           // per-(mt,kt) cumulative h-ready (2 producers)

__device__ __forceinline__ float sigf(float x) {
    return __fdividef(1.0f, 1.0f + __expf(-x));
}
__device__ __forceinline__ float tanhfast(float x) {
    return 2.0f * sigf(2.0f * x) - 1.0f;
}

#define SW128(off) ((off) ^ (((off) >> 3) & 0x70))

__device__ __forceinline__ uint32_t smem_u32(const void* p) {
    uint32_t a;
    asm("{ .reg .u64 t; cvta.to.shared.u64 t, %1; cvt.u32.u64 %0, t; }" : "=r"(a) : "l"(p));
    return a;
}

#define MBAR_INIT(addr, cnt) \
    asm volatile("mbarrier.init.shared.b64 [%0], %1;" :: "r"(addr), "r"(cnt) : "memory")
#define MBAR_EXPECT(addr, bytes) \
    asm volatile("mbarrier.arrive.expect_tx.shared.b64 _, [%0], %1;" :: "r"(addr), "r"(bytes) : "memory")
#define FENCE_ASYNC() asm volatile("fence.proxy.async.shared::cta;" ::: "memory")

#define MBAR_WAIT_PARITY(addr, par) do {                                        \
    uint32_t _m = (addr); uint32_t _p = (par); uint32_t _d;                     \
    asm volatile("{\n\t.reg .pred p;\n\t"                                       \
        "mbarrier.try_wait.parity.acquire.cta.shared::cta.b64 p, [%1], %2;\n\t" \
        "selp.b32 %0, 1, 0, p;\n\t}" : "=r"(_d) : "r"(_m), "r"(_p) : "memory"); \
    if (!_d) {                                                                  \
        asm volatile("{\n\t.reg .pred P1;\n\t"                                  \
        "WL_%=:\n\t"                                                            \
        "mbarrier.try_wait.parity.acquire.cta.shared::cta.b64 P1, [%0], %1, 0x989680;\n\t" \
        "@P1 bra.uni WD_%=;\n\t"                                                \
        "bra.uni WL_%=;\n\t"                                                    \
        "WD_%=:\n\t}" :: "r"(_m), "r"(_p) : "memory");                          \
    }                                                                           \
} while (0)

#define BULK_G2S(dst, src, bytes, mbar) \
    asm volatile("cp.async.bulk.shared::cta.global.mbarrier::complete_tx::bytes [%0], [%1], %2, [%3];" \
        :: "r"(dst), "l"(src), "r"((uint32_t)(bytes)), "r"(mbar) : "memory")

__device__ __forceinline__ void ldsm4(uint32_t (&r)[4], uint32_t addr) {
    asm volatile("ldmatrix.sync.aligned.m8n8.x4.shared.b16 {%0,%1,%2,%3}, [%4];"
        : "=r"(r[0]), "=r"(r[1]), "=r"(r[2]), "=r"(r[3]) : "r"(addr));
}
__device__ __forceinline__ void mma16816(float (&c)[4], const uint32_t (&a)[4],
                                         uint32_t b0, uint32_t b1) {
    asm volatile(
        "mma.sync.aligned.m16n8k16.row.col.f32.f16.f16.f32 "
        "{%0,%1,%2,%3}, {%4,%5,%6,%7}, {%8,%9}, {%0,%1,%2,%3};"
        : "+f"(c[0]), "+f"(c[1]), "+f"(c[2]), "+f"(c[3])
        : "r"(a[0]), "r"(a[1]), "r"(a[2]), "r"(a[3]), "r"(b0), "r"(b1));
}

// ---------------- init ------------------------------------------------------
__global__ void init_kernel(float* __restrict__ out, const float* __restrict__ bv) {
    int i = blockIdx.x * blockDim.x + threadIdx.x;
    if (i < 262144) ((uint32_t*)&g_hT[0][0][0][0])[i] = 0u;   // zero h0 tiles
    if (i < ROWS) out[i] = bv[0];
    if (i < 64) ((unsigned*)g_hrdy)[i] = 0u;
}

// ---------------- obs -> fp16 swizzled tiles ---------------------------------
__global__ void obs_conv_kernel(const float* __restrict__ obs) {
    int i = blockIdx.x * blockDim.x + threadIdx.x;
    int d = (i & 63) * 2;
    int r = i >> 6;
    int t = r >> 10, n = r & 1023;
    size_t off = (size_t)(n >> 3) * 131072 + (size_t)t * 1024 + (size_t)(n & 7) * 128 + d;
    float2 v = *(const float2*)(obs + off);
    __half h0 = __float2half_rn(v.x);
    __half h1 = __float2half_rn(v.y);
    uint32_t ph = (uint32_t)__half_as_ushort(h0) | ((uint32_t)__half_as_ushort(h1) << 16);
    int rt = r >> 7, mloc = r & 127, kt = d >> 6, c = d & 63;
    *(uint32_t*)((char*)&g_oT[rt][kt][0] + SW128((uint32_t)(mloc * 128 + c * 2))) = ph;
}

// ---------------- prep: gate-triple reorder, single fp16 --------------------
__global__ void prep_kernel(const float* __restrict__ W_ih, const float* __restrict__ W_hh,
                            const float* __restrict__ W1) {
    int idx = blockIdx.x * blockDim.x + threadIdx.x;   // 786432
    if (idx >= G_DIM * H_DIM) return;
    int k = idx & 511, kt = k >> 6, c = k & 63;
    int jtr = idx >> 9;
    int jc = jtr / 96, rem = jtr % 96;
    int gt = rem >> 5, jl = rem & 31;
    size_t srow = (size_t)(gt * 512 + jc * 32 + jl);
    uint32_t off = SW128((uint32_t)(rem * 128 + c * 2));
    *(__half*)((char*)&g_WhhT[jc][kt][0] + off) = __float2half_rn(W_hh[srow * H_DIM + k]);
    *(__half*)((char*)&g_WihT[jc][kt][0] + off) = __float2half_rn(W_ih[srow * H_DIM + k]);
    if (idx < 65536) {
        int n = idx >> 7, d = idx & 127;
        int nt = n >> 7, m = n & 127;
        int ktd = d >> 6, cd = d & 63;
        uint32_t o2 = SW128((uint32_t)(m * 128 + cd * 2));
        *(__half*)((char*)&g_W1T[nt][ktd][0] + o2) = __float2half_rn(W1[idx]);
    }
}

// ---------------- gemm1: x = relu(obs @ W1^T + b1)  (fp16 HMMA) -------------
__global__ __launch_bounds__(256, 2) void gemm1_kernel(const float* __restrict__ b1)
{
    extern __shared__ char smem[];
    const uint32_t sb = smem_u32(smem);
    const int tid = threadIdx.x;
    const int wid = tid >> 5, lane = tid & 31;
    const int mw = wid >> 1, nw = wid & 1;
    const int nt = blockIdx.x;
    const int rt = blockIdx.y;

    if (tid == 0) {
        MBAR_INIT(sb, 1);
        MBAR_INIT(sb + 8, 1);
        FENCE_ASYNC();
    }
    __syncthreads();

    float c[2][8][4] = {};

    if (tid == 0) {
#pragma unroll
        for (int ch = 0; ch < 2; ch++) {
            uint32_t mb = sb + ch * 8;
            uint32_t base = sb + 1024 + ch * 32768;
            MBAR_EXPECT(mb, 32768);
            BULK_G2S(base,         &g_oT[rt][ch][0],  16384, mb);
            BULK_G2S(base + 16384, &g_W1T[nt][ch][0], 16384, mb);
        }
    }

    for (int ch = 0; ch < 2; ch++) {
        MBAR_WAIT_PARITY(sb + ch * 8, 0);
        const uint32_t base = sb + 1024 + ch * 32768;
        const uint32_t sA = base, sB = base + 16384;
#pragma unroll
        for (int ks = 0; ks < 4; ks++) {
            uint32_t a[2][4];
            uint32_t arow0 = mw * 32 + (lane & 15);
            uint32_t acol = ks * 16 + ((lane >> 4) << 3);
#pragma unroll
            for (int mi = 0; mi < 2; mi++)
                ldsm4(a[mi], sA + SW128((arow0 + mi * 16) * 128 + acol * 2));
#pragma unroll
            for (int bp = 0; bp < 4; bp++) {
                uint32_t bh[4];
                uint32_t brow = nw * 64 + bp * 16 + (lane & 7) + ((lane >> 4) & 1) * 8;
                uint32_t bcol = ks * 16 + ((lane >> 3) & 1) * 8;
                ldsm4(bh, sB + SW128(brow * 128 + bcol * 2));
#pragma unroll
                for (int mi = 0; mi < 2; mi++) {
                    mma16816(c[mi][2 * bp],     a[mi], bh[0], bh[1]);
                    mma16816(c[mi][2 * bp + 1], a[mi], bh[2], bh[3]);
                }
            }
        }
    }

    const int n0 = nt * 128;
    const int g = lane >> 2, ct = lane & 3;
#pragma unroll
    for (int mi = 0; mi < 2; mi++) {
#pragma unroll
        for (int ntl = 0; ntl < 8; ntl++) {
            int mloc = mw * 32 + mi * 16 + g;
            int col = n0 + nw * 64 + ntl * 8 + ct * 2;
            float2 bi = *(const float2*)(b1 + col);
            float v0x = fmaxf(c[mi][ntl][0] + bi.x, 0.0f);
            float v0y = fmaxf(c[mi][ntl][1] + bi.y, 0.0f);
            float v1x = fmaxf(c[mi][ntl][2] + bi.x, 0.0f);
            float v1y = fmaxf(c[mi][ntl][3] + bi.y, 0.0f);
            int kt = col >> 6, cc = col & 63;
            uint32_t p0 = (uint32_t)__half_as_ushort(__float2half_rn(v0x))
                        | ((uint32_t)__half_as_ushort(__float2half_rn(v0y)) << 16);
            uint32_t p1 = (uint32_t)__half_as_ushort(__float2half_rn(v1x))
                        | ((uint32_t)__half_as_ushort(__float2half_rn(v1y)) << 16);
            *(uint32_t*)((char*)&g_xT[rt][kt][0] + SW128((uint32_t)(mloc * 128 + cc * 2)))       = p0;
            *(uint32_t*)((char*)&g_xT[rt][kt][0] + SW128((uint32_t)((mloc + 8) * 128 + cc * 2))) = p1;
        }
    }
}

// ---------------- fused persistent GRU scan ---------------------------------
// R15 champion (asymmetric per-chunk barrier) + fine-grained h-readiness:
// per-(mt,kt) cumulative 2-producer counters replace the all-16 grid barrier.
// Boundary: fence+sync, publish own tile, tid0 issues h chunks 0-3 with
// pair-local polls; no global spin, no trailing sync. Mid-step h chunks 4-7
// issued (with polls) by the rotating issuer warp - non-blocking for others.
// total smem = 1024 + 4*57344 = 230400.
#define STG 57344
#define OFF_X  16384
#define OFF_WH 32768
#define OFF_WI 45056

__global__ __launch_bounds__(256, 1) void gru_persist_kernel(
    const float* __restrict__ b_hh, const float* __restrict__ b_ih,
    const float* __restrict__ Wv, float* __restrict__ out)
{
    extern __shared__ char smem[];
    const uint32_t sb = smem_u32(smem);
    const int tid = threadIdx.x;
    const int wid = tid >> 5, lane = tid & 31;
    const int jc = blockIdx.x;    // 0..15
    const int mt = blockIdx.y;    // 0..7

    // mbars: pH[4] @ sb+0..24, pX[4] @ sb+32..56
    if (tid == 0) {
#pragma unroll
        for (int b = 0; b < 4; b++) {
            MBAR_INIT(sb + b * 8, 1);
            MBAR_INIT(sb + 32 + b * 8, 1);
        }
        FENCE_ASYNC();
    }
    __syncthreads();

    const uint32_t S0 = sb + 1024;

    auto issueH = [&](int t, int ch) {
        int buf = ch & 3;
        unsigned need = 2u * (unsigned)t;
        if (need) {
            while (((volatile unsigned*)&g_hrdy[mt][ch])[0] < need) { }
            __threadfence();
        }
        uint32_t mb = sb + buf * 8;
        MBAR_EXPECT(mb, 16384);
        BULK_G2S(S0 + buf * STG, &g_hT[t & 1][mt][ch][0], 16384, mb);
    };
    auto issueXW = [&](int t, int ch) {
        int buf = ch & 3;
        uint32_t mb = sb + 32 + buf * 8;
        uint32_t base = S0 + buf * STG;
        MBAR_EXPECT(mb, 40960);
        BULK_G2S(base + OFF_X,  &g_xT[t * 8 + mt][ch][0], 16384, mb);
        BULK_G2S(base + OFF_WH, &g_WhhT[jc][ch][0],       12288, mb);
        BULK_G2S(base + OFF_WI, &g_WihT[jc][ch][0],       12288, mb);
    };

    if (tid == 0) {
#pragma unroll
        for (int c2 = 0; c2 < 4; c2++) { issueXW(0, c2); issueH(0, c2); }
    }

    // per-thread constants
    const int g = lane >> 2, ct = lane & 3;
    const int jbase = jc * 32;
    const uint32_t arow = wid * 16 + (lane & 15);
    float2 brv[4], bzv[4], bniv[4], bnhv[4], wvv[4];
#pragma unroll
    for (int jj = 0; jj < 4; jj++) {
        int j = jbase + jj * 8 + ct * 2;
        float2 ir = *(const float2*)(b_ih + j);
        float2 hr = *(const float2*)(b_hh + j);
        brv[jj].x = ir.x + hr.x; brv[jj].y = ir.y + hr.y;
        float2 iz = *(const float2*)(b_ih + 512 + j);
        float2 hz = *(const float2*)(b_hh + 512 + j);
        bzv[jj].x = iz.x + hz.x; bzv[jj].y = iz.y + hz.y;
        bniv[jj] = *(const float2*)(b_ih + 1024 + j);
        bnhv[jj] = *(const float2*)(b_hh + 1024 + j);
        wvv[jj]  = *(const float2*)(Wv + j);
    }
    float hreg[2][4][2];
#pragma unroll
    for (int mi = 0; mi < 2; mi++)
#pragma unroll
        for (int jj = 0; jj < 4; jj++)
            hreg[mi][jj][0] = hreg[mi][jj][1] = 0.0f;

    int pH[4] = {0, 0, 0, 0}, pX[4] = {0, 0, 0, 0};

    for (int t = 0; t < T_LEN; t++) {
        float cg[12][4] = {};
        float ci[12][4] = {};

        for (int ch = 0; ch < 8; ch++) {
            const int buf = ch & 3;
            MBAR_WAIT_PARITY(sb + buf * 8, pH[buf]);       pH[buf] ^= 1;
            MBAR_WAIT_PARITY(sb + 32 + buf * 8, pX[buf]);  pX[buf] ^= 1;
            const uint32_t base = S0 + buf * STG;

#pragma unroll
            for (int ks = 0; ks < 4; ks++) {
                uint32_t ah[4], ax[4];
                uint32_t acol = ks * 16 + ((lane >> 4) << 3);
                uint32_t aoff = SW128(arow * 128 + acol * 2);
                ldsm4(ah, base + aoff);
                ldsm4(ax, base + OFF_X + aoff);
#pragma unroll
                for (int bt = 0; bt < 6; bt++) {
                    uint32_t wh[4], wi[4];
                    uint32_t brow = bt * 16 + (lane & 7) + ((lane >> 4) & 1) * 8;
                    uint32_t bcol = ks * 16 + ((lane >> 3) & 1) * 8;
                    uint32_t boff = SW128(brow * 128 + bcol * 2);
                    ldsm4(wh, base + OFF_WH + boff);
                    ldsm4(wi, base + OFF_WI + boff);
                    mma16816(cg[2 * bt],     ah, wh[0], wh[1]);
                    mma16816(cg[2 * bt + 1], ah, wh[2], wh[3]);
                    mma16816(ci[2 * bt],     ax, wi[0], wi[1]);
                    mma16816(ci[2 * bt + 1], ax, wi[2], wi[3]);
                }
            }
            // asymmetric barrier: issuer warp (= ch) blocks, others just arrive
            const int barid = 2 + (ch & 3);
            if (wid == ch) {
                asm volatile("bar.sync %0, 256;" :: "r"(barid) : "memory");
                if (lane == 0) {
                    if (ch < 4) {
                        issueH(t, ch + 4);        // poll pair-local, non-blocking for others
                        issueXW(t, ch + 4);
                    } else if (t + 1 < T_LEN) {
                        issueXW(t + 1, ch - 4);   // next-step x/W into freed buffer
                    }
                }
            } else {
                asm volatile("bar.arrive %0, 256;" :: "r"(barid) : "memory");
            }
        }

        // ---------------- fused epilogue ----------------
        const int wr = (t + 1) & 1;
#pragma unroll
        for (int mi = 0; mi < 2; mi++) {
            int mloc = wid * 16 + g + mi * 8;
            int m_g = mt * 128 + mloc;

            float vp = 0.0f;
#pragma unroll
            for (int jj = 0; jj < 4; jj++) {
                int jl = jj * 8 + ct * 2;
                int j  = jbase + jl;

                float r0 = sigf(ci[jj][mi * 2]     + cg[jj][mi * 2]     + brv[jj].x);
                float r1 = sigf(ci[jj][mi * 2 + 1] + cg[jj][mi * 2 + 1] + brv[jj].y);
                float z0 = sigf(ci[4 + jj][mi * 2]     + cg[4 + jj][mi * 2]     + bzv[jj].x);
                float z1 = sigf(ci[4 + jj][mi * 2 + 1] + cg[4 + jj][mi * 2 + 1] + bzv[jj].y);
                float nt0 = tanhfast(ci[8 + jj][mi * 2]     + bniv[jj].x
                                     + r0 * (cg[8 + jj][mi * 2]     + bnhv[jj].x));
                float nt1 = tanhfast(ci[8 + jj][mi * 2 + 1] + bniv[jj].y
                                     + r1 * (cg[8 + jj][mi * 2 + 1] + bnhv[jj].y));
                float h0 = (1.0f - z0) * nt0 + z0 * hreg[mi][jj][0];
                float h1 = (1.0f - z1) * nt1 + z1 * hreg[mi][jj][1];
                hreg[mi][jj][0] = h0;
                hreg[mi][jj][1] = h1;

                __half hh0 = __float2half_rn(h0);
                __half hh1 = __float2half_rn(h1);
                uint32_t ph = (uint32_t)__half_as_ushort(hh0) | ((uint32_t)__half_as_ushort(hh1) << 16);
                int kt = j >> 6, cc = j & 63;
                uint32_t off = SW128((uint32_t)(mloc * 128 + cc * 2));
                *(uint32_t*)((char*)&g_hT[wr][mt][kt][0] + off) = ph;

                vp = fmaf(wvv[jj].x, h0, vp);
                vp = fmaf(wvv[jj].y, h1, vp);
            }
            vp += __shfl_xor_sync(0xffffffffu, vp, 1);
            vp += __shfl_xor_sync(0xffffffffu, vp, 2);
            if (ct == 0) {
                int bs = m_g >> 3, a = m_g & 7;
                atomicAdd(&out[((size_t)bs * T_LEN + t) * 8 + a], vp);
            }
        }

        // ---- boundary: publish own tile, issue next-step h (pair-local) ----
        if (t < T_LEN - 1) {
            __threadfence();
            __syncthreads();
            if (tid == 0) {
                atomicAdd(&g_hrdy[mt][jc >> 1], 1u);
#pragma unroll
                for (int c2 = 0; c2 < 4; c2++) issueH(t + 1, c2);
            }
            // no trailing sync: consumers block on chunk-0 mbars
        }
    }
}

// ---------------------------------------------------------------------------
extern "C" void kernel_launch(void* const* d_in, const int* in_sizes, int n_in,
                              void* d_out, int out_size)
{
    const float* obs  = (const float*)d_in[0];
    const float* W1   = (const float*)d_in[1];
    const float* b1   = (const float*)d_in[2];
    const float* W_ih = (const float*)d_in[3];
    const float* b_ih = (const float*)d_in[4];
    const float* W_hh = (const float*)d_in[5];
    const float* b_hh = (const float*)d_in[6];
    const float* Wv   = (const float*)d_in[7];
    const float* bv   = (const float*)d_in[8];
    float* out = (float*)d_out;

    cudaFuncSetAttribute(gemm1_kernel,       cudaFuncAttributeMaxDynamicSharedMemorySize, 66560);
    cudaFuncSetAttribute(gru_persist_kernel, cudaFuncAttributeMaxDynamicSharedMemorySize, 230400);

    init_kernel<<<2048, 256>>>(out, bv);
    obs_conv_kernel<<<32768, 256>>>(obs);
    prep_kernel<<<3072, 256>>>(W_ih, W_hh, W1);
    gemm1_kernel<<<dim3(4, 1024), 256, 66560>>>(b1);
    gru_persist_kernel<<<dim3(16, 8), 256, 230400>>>(b_hh, b_ih, Wv, out);
}

// round 17
// speedup vs baseline: 1.2148x; 1.2148x over previous
#include <cuda_runtime.h>
#include <cuda_fp16.h>
#include <math.h>
#include <stdint.h>

#define T_LEN 128
#define NB    1024
#define D_IN  128
#define H_DIM 512
#define G_DIM 1536
#define ROWS  (T_LEN * NB)     // 131072

// ---------------- scratch (__device__ globals) ------------------------------
__device__ __half g_oT[1024][2][8192];      // obs fp16 tiles [rt][kt] 128x64, SW128
__device__ __half g_W1T[4][2][8192];        // W1 tiles [nt][kt] 128x64
__device__ __half g_xT[1024][8][8192];      // x fp16 tiles [rt][kt] 128x64, SW128
// Combined weights: per (jc, k2): Whh(kt=2k2) 12288B | Whh(2k2+1) | Wih(2k2) | Wih(2k2+1)
__device__ __half g_WT[16][4][24576];
__device__ __half g_hT[2][8][8][8192];      // h fp16 tiles ping-pong [mt][kt] 128x64
__device__ unsigned g_arrm[8][T_LEN];       // per-mt, per-step barrier counters

__device__ __forceinline__ float sigf(float x) {
    return __fdividef(1.0f, 1.0f + __expf(-x));
}
__device__ __forceinline__ float tanhfast(float x) {
    return 2.0f * sigf(2.0f * x) - 1.0f;
}

#define SW128(off) ((off) ^ (((off) >> 3) & 0x70))

__device__ __forceinline__ uint32_t smem_u32(const void* p) {
    uint32_t a;
    asm("{ .reg .u64 t; cvta.to.shared.u64 t, %1; cvt.u32.u64 %0, t; }" : "=r"(a) : "l"(p));
    return a;
}

#define MBAR_INIT(addr, cnt) \
    asm volatile("mbarrier.init.shared.b64 [%0], %1;" :: "r"(addr), "r"(cnt) : "memory")
#define MBAR_EXPECT(addr, bytes) \
    asm volatile("mbarrier.arrive.expect_tx.shared.b64 _, [%0], %1;" :: "r"(addr), "r"(bytes) : "memory")
#define FENCE_ASYNC() asm volatile("fence.proxy.async.shared::cta;" ::: "memory")

#define MBAR_WAIT_PARITY(addr, par) do {                                        \
    uint32_t _m = (addr); uint32_t _p = (par); uint32_t _d;                     \
    asm volatile("{\n\t.reg .pred p;\n\t"                                       \
        "mbarrier.try_wait.parity.acquire.cta.shared::cta.b64 p, [%1], %2;\n\t" \
        "selp.b32 %0, 1, 0, p;\n\t}" : "=r"(_d) : "r"(_m), "r"(_p) : "memory"); \
    if (!_d) {                                                                  \
        asm volatile("{\n\t.reg .pred P1;\n\t"                                  \
        "WL_%=:\n\t"                                                            \
        "mbarrier.try_wait.parity.acquire.cta.shared::cta.b64 P1, [%0], %1, 0x989680;\n\t" \
        "@P1 bra.uni WD_%=;\n\t"                                                \
        "bra.uni WL_%=;\n\t"                                                    \
        "WD_%=:\n\t}" :: "r"(_m), "r"(_p) : "memory");                          \
    }                                                                           \
} while (0)

#define BULK_G2S(dst, src, bytes, mbar) \
    asm volatile("cp.async.bulk.shared::cta.global.mbarrier::complete_tx::bytes [%0], [%1], %2, [%3];" \
        :: "r"(dst), "l"(src), "r"((uint32_t)(bytes)), "r"(mbar) : "memory")

__device__ __forceinline__ void ldsm4(uint32_t (&r)[4], uint32_t addr) {
    asm volatile("ldmatrix.sync.aligned.m8n8.x4.shared.b16 {%0,%1,%2,%3}, [%4];"
        : "=r"(r[0]), "=r"(r[1]), "=r"(r[2]), "=r"(r[3]) : "r"(addr));
}
__device__ __forceinline__ void mma16816(float (&c)[4], const uint32_t (&a)[4],
                                         uint32_t b0, uint32_t b1) {
    asm volatile(
        "mma.sync.aligned.m16n8k16.row.col.f32.f16.f16.f32 "
        "{%0,%1,%2,%3}, {%4,%5,%6,%7}, {%8,%9}, {%0,%1,%2,%3};"
        : "+f"(c[0]), "+f"(c[1]), "+f"(c[2]), "+f"(c[3])
        : "r"(a[0]), "r"(a[1]), "r"(a[2]), "r"(a[3]), "r"(b0), "r"(b1));
}

// ---------------- init ------------------------------------------------------
__global__ void init_kernel(float* __restrict__ out, const float* __restrict__ bv) {
    int i = blockIdx.x * blockDim.x + threadIdx.x;
    if (i < 262144) ((uint32_t*)&g_hT[0][0][0][0])[i] = 0u;   // zero h0 tiles
    if (i < ROWS) out[i] = bv[0];
    if (i < 8 * T_LEN) ((unsigned*)g_arrm)[i] = 0u;
}

// ---------------- obs -> fp16 swizzled tiles ---------------------------------
__global__ void obs_conv_kernel(const float* __restrict__ obs) {
    int i = blockIdx.x * blockDim.x + threadIdx.x;
    int d = (i & 63) * 2;
    int r = i >> 6;
    int t = r >> 10, n = r & 1023;
    size_t off = (size_t)(n >> 3) * 131072 + (size_t)t * 1024 + (size_t)(n & 7) * 128 + d;
    float2 v = *(const float2*)(obs + off);
    __half h0 = __float2half_rn(v.x);
    __half h1 = __float2half_rn(v.y);
    uint32_t ph = (uint32_t)__half_as_ushort(h0) | ((uint32_t)__half_as_ushort(h1) << 16);
    int rt = r >> 7, mloc = r & 127, kt = d >> 6, c = d & 63;
    *(uint32_t*)((char*)&g_oT[rt][kt][0] + SW128((uint32_t)(mloc * 128 + c * 2))) = ph;
}

// ---------------- prep: gate-triple reorder into combined W block -----------
__global__ void prep_kernel(const float* __restrict__ W_ih, const float* __restrict__ W_hh,
                            const float* __restrict__ W1) {
    int idx = blockIdx.x * blockDim.x + threadIdx.x;   // 786432
    if (idx >= G_DIM * H_DIM) return;
    int k = idx & 511, kt = k >> 6, c = k & 63;
    int jtr = idx >> 9;
    int jc = jtr / 96, rem = jtr % 96;
    int gt = rem >> 5, jl = rem & 31;
    size_t srow = (size_t)(gt * 512 + jc * 32 + jl);
    uint32_t off = SW128((uint32_t)(rem * 128 + c * 2));
    char* wb = (char*)&g_WT[jc][kt >> 1][0];
    *(__half*)(wb + (kt & 1) * 12288 + off)         = __float2half_rn(W_hh[srow * H_DIM + k]);
    *(__half*)(wb + 24576 + (kt & 1) * 12288 + off) = __float2half_rn(W_ih[srow * H_DIM + k]);
    if (idx < 65536) {
        int n = idx >> 7, d = idx & 127;
        int nt = n >> 7, m = n & 127;
        int ktd = d >> 6, cd = d & 63;
        uint32_t o2 = SW128((uint32_t)(m * 128 + cd * 2));
        *(__half*)((char*)&g_W1T[nt][ktd][0] + o2) = __float2half_rn(W1[idx]);
    }
}

// ---------------- gemm1: x = relu(obs @ W1^T + b1)  (fp16 HMMA) -------------
__global__ __launch_bounds__(256, 2) void gemm1_kernel(const float* __restrict__ b1)
{
    extern __shared__ char smem[];
    const uint32_t sb = smem_u32(smem);
    const int tid = threadIdx.x;
    const int wid = tid >> 5, lane = tid & 31;
    const int mw = wid >> 1, nw = wid & 1;
    const int nt = blockIdx.x;
    const int rt = blockIdx.y;

    if (tid == 0) {
        MBAR_INIT(sb, 1);
        MBAR_INIT(sb + 8, 1);
        FENCE_ASYNC();
    }
    __syncthreads();

    float c[2][8][4] = {};

    if (tid == 0) {
#pragma unroll
        for (int ch = 0; ch < 2; ch++) {
            uint32_t mb = sb + ch * 8;
            uint32_t base = sb + 1024 + ch * 32768;
            MBAR_EXPECT(mb, 32768);
            BULK_G2S(base,         &g_oT[rt][ch][0],  16384, mb);
            BULK_G2S(base + 16384, &g_W1T[nt][ch][0], 16384, mb);
        }
    }

    for (int ch = 0; ch < 2; ch++) {
        MBAR_WAIT_PARITY(sb + ch * 8, 0);
        const uint32_t base = sb + 1024 + ch * 32768;
        const uint32_t sA = base, sB = base + 16384;
#pragma unroll
        for (int ks = 0; ks < 4; ks++) {
            uint32_t a[2][4];
            uint32_t arow0 = mw * 32 + (lane & 15);
            uint32_t acol = ks * 16 + ((lane >> 4) << 3);
#pragma unroll
            for (int mi = 0; mi < 2; mi++)
                ldsm4(a[mi], sA + SW128((arow0 + mi * 16) * 128 + acol * 2));
#pragma unroll
            for (int bp = 0; bp < 4; bp++) {
                uint32_t bh[4];
                uint32_t brow = nw * 64 + bp * 16 + (lane & 7) + ((lane >> 4) & 1) * 8;
                uint32_t bcol = ks * 16 + ((lane >> 3) & 1) * 8;
                ldsm4(bh, sB + SW128(brow * 128 + bcol * 2));
#pragma unroll
                for (int mi = 0; mi < 2; mi++) {
                    mma16816(c[mi][2 * bp],     a[mi], bh[0], bh[1]);
                    mma16816(c[mi][2 * bp + 1], a[mi], bh[2], bh[3]);
                }
            }
        }
    }

    const int n0 = nt * 128;
    const int g = lane >> 2, ct = lane & 3;
#pragma unroll
    for (int mi = 0; mi < 2; mi++) {
#pragma unroll
        for (int ntl = 0; ntl < 8; ntl++) {
            int mloc = mw * 32 + mi * 16 + g;
            int col = n0 + nw * 64 + ntl * 8 + ct * 2;
            float2 bi = *(const float2*)(b1 + col);
            float v0x = fmaxf(c[mi][ntl][0] + bi.x, 0.0f);
            float v0y = fmaxf(c[mi][ntl][1] + bi.y, 0.0f);
            float v1x = fmaxf(c[mi][ntl][2] + bi.x, 0.0f);
            float v1y = fmaxf(c[mi][ntl][3] + bi.y, 0.0f);
            int kt = col >> 6, cc = col & 63;
            uint32_t p0 = (uint32_t)__half_as_ushort(__float2half_rn(v0x))
                        | ((uint32_t)__half_as_ushort(__float2half_rn(v0y)) << 16);
            uint32_t p1 = (uint32_t)__half_as_ushort(__float2half_rn(v1x))
                        | ((uint32_t)__half_as_ushort(__float2half_rn(v1y)) << 16);
            *(uint32_t*)((char*)&g_xT[rt][kt][0] + SW128((uint32_t)(mloc * 128 + cc * 2)))       = p0;
            *(uint32_t*)((char*)&g_xT[rt][kt][0] + SW128((uint32_t)((mloc + 8) * 128 + cc * 2))) = p1;
        }
    }
}

// ---------------- fused persistent GRU scan ---------------------------------
// R15 champion re-chunked: 4 chunks of K=128/step, 2 stages of 112KB.
// Stage: h@0 (32K), x@32768 (32K), W@65536 (48K = Whh s0|Whh s1|Wih s0|Wih s1).
// ONE mbar per buffer (init-count 2: xW-expect + h-expect accumulate tx).
// Asymmetric per-chunk barrier: issuer warp (= ch) bar.sync, others bar.arrive.
// Boundary: R15's (fence, sync, tid0 atomic+spin16, issue h0/h1, sync).
// total smem = 1024 + 2*114688 = 230400.
#define STG   114688
#define OFF_X 32768
#define OFF_W 65536

__global__ __launch_bounds__(256, 1) void gru_persist_kernel(
    const float* __restrict__ b_hh, const float* __restrict__ b_ih,
    const float* __restrict__ Wv, float* __restrict__ out)
{
    extern __shared__ char smem[];
    const uint32_t sb = smem_u32(smem);
    const int tid = threadIdx.x;
    const int wid = tid >> 5, lane = tid & 31;
    const int jc = blockIdx.x;    // 0..15
    const int mt = blockIdx.y;    // 0..7

    // mbars: mb[2] @ sb+0/8, init-count 2 (two expect-arrivals per phase)
    if (tid == 0) {
        MBAR_INIT(sb, 2);
        MBAR_INIT(sb + 8, 2);
        FENCE_ASYNC();
    }
    __syncthreads();

    const uint32_t S0 = sb + 1024;

    auto issueH = [&](int t, int ch) {
        int buf = ch & 1;
        uint32_t mb = sb + buf * 8;
        MBAR_EXPECT(mb, 32768);
        BULK_G2S(S0 + buf * STG, &g_hT[t & 1][mt][2 * ch][0], 32768, mb);
    };
    auto issueXW = [&](int t, int ch) {
        int buf = ch & 1;
        uint32_t mb = sb + buf * 8;
        uint32_t base = S0 + buf * STG;
        MBAR_EXPECT(mb, 81920);
        BULK_G2S(base + OFF_X, &g_xT[t * 8 + mt][2 * ch][0], 32768, mb);
        BULK_G2S(base + OFF_W, &g_WT[jc][ch][0],             49152, mb);
    };

    if (tid == 0) {
#pragma unroll
        for (int c2 = 0; c2 < 2; c2++) { issueXW(0, c2); issueH(0, c2); }
    }

    // per-thread constants
    const int g = lane >> 2, ct = lane & 3;
    const int jbase = jc * 32;
    const uint32_t arow = wid * 16 + (lane & 15);
    float2 brv[4], bzv[4], bniv[4], bnhv[4], wvv[4];
#pragma unroll
    for (int jj = 0; jj < 4; jj++) {
        int j = jbase + jj * 8 + ct * 2;
        float2 ir = *(const float2*)(b_ih + j);
        float2 hr = *(const float2*)(b_hh + j);
        brv[jj].x = ir.x + hr.x; brv[jj].y = ir.y + hr.y;
        float2 iz = *(const float2*)(b_ih + 512 + j);
        float2 hz = *(const float2*)(b_hh + 512 + j);
        bzv[jj].x = iz.x + hz.x; bzv[jj].y = iz.y + hz.y;
        bniv[jj] = *(const float2*)(b_ih + 1024 + j);
        bnhv[jj] = *(const float2*)(b_hh + 1024 + j);
        wvv[jj]  = *(const float2*)(Wv + j);
    }
    float hreg[2][4][2];
#pragma unroll
    for (int mi = 0; mi < 2; mi++)
#pragma unroll
        for (int jj = 0; jj < 4; jj++)
            hreg[mi][jj][0] = hreg[mi][jj][1] = 0.0f;

    int pB[2] = {0, 0};

    for (int t = 0; t < T_LEN; t++) {
        float cg[12][4] = {};
        float ci[12][4] = {};

        for (int ch = 0; ch < 4; ch++) {
            const int buf = ch & 1;
            MBAR_WAIT_PARITY(sb + buf * 8, pB[buf]);  pB[buf] ^= 1;
            const uint32_t base = S0 + buf * STG;

#pragma unroll
            for (int ks = 0; ks < 8; ks++) {
                const int kk = ks >> 2, ks4 = ks & 3;
                uint32_t ah[4], ax[4];
                uint32_t acol = ks4 * 16 + ((lane >> 4) << 3);
                uint32_t aoff = SW128(arow * 128 + acol * 2) + kk * 16384;
                ldsm4(ah, base + aoff);
                ldsm4(ax, base + OFF_X + aoff);
#pragma unroll
                for (int bt = 0; bt < 6; bt++) {
                    uint32_t wh[4], wi[4];
                    uint32_t brow = bt * 16 + (lane & 7) + ((lane >> 4) & 1) * 8;
                    uint32_t bcol = ks4 * 16 + ((lane >> 3) & 1) * 8;
                    uint32_t boff = SW128(brow * 128 + bcol * 2) + kk * 12288;
                    ldsm4(wh, base + OFF_W + boff);
                    ldsm4(wi, base + OFF_W + 24576 + boff);
                    mma16816(cg[2 * bt],     ah, wh[0], wh[1]);
                    mma16816(cg[2 * bt + 1], ah, wh[2], wh[3]);
                    mma16816(ci[2 * bt],     ax, wi[0], wi[1]);
                    mma16816(ci[2 * bt + 1], ax, wi[2], wi[3]);
                }
            }
            // asymmetric barrier: issuer warp (= ch) blocks, others just arrive
            const int barid = 2 + buf;
            if (wid == ch) {
                asm volatile("bar.sync %0, 256;" :: "r"(barid) : "memory");
                if (lane == 0) {
                    if (ch < 2) {
                        issueXW(t, ch + 2);
                        issueH(t, ch + 2);
                    } else if (t + 1 < T_LEN) {
                        issueXW(t + 1, ch - 2);   // next-step x/W into freed buffer
                    }
                }
            } else {
                asm volatile("bar.arrive %0, 256;" :: "r"(barid) : "memory");
            }
        }

        // ---------------- fused epilogue ----------------
        const int wr = (t + 1) & 1;
#pragma unroll
        for (int mi = 0; mi < 2; mi++) {
            int mloc = wid * 16 + g + mi * 8;
            int m_g = mt * 128 + mloc;

            float vp = 0.0f;
#pragma unroll
            for (int jj = 0; jj < 4; jj++) {
                int jl = jj * 8 + ct * 2;
                int j  = jbase + jl;

                float r0 = sigf(ci[jj][mi * 2]     + cg[jj][mi * 2]     + brv[jj].x);
                float r1 = sigf(ci[jj][mi * 2 + 1] + cg[jj][mi * 2 + 1] + brv[jj].y);
                float z0 = sigf(ci[4 + jj][mi * 2]     + cg[4 + jj][mi * 2]     + bzv[jj].x);
                float z1 = sigf(ci[4 + jj][mi * 2 + 1] + cg[4 + jj][mi * 2 + 1] + bzv[jj].y);
                float nt0 = tanhfast(ci[8 + jj][mi * 2]     + bniv[jj].x
                                     + r0 * (cg[8 + jj][mi * 2]     + bnhv[jj].x));
                float nt1 = tanhfast(ci[8 + jj][mi * 2 + 1] + bniv[jj].y
                                     + r1 * (cg[8 + jj][mi * 2 + 1] + bnhv[jj].y));
                float h0 = (1.0f - z0) * nt0 + z0 * hreg[mi][jj][0];
                float h1 = (1.0f - z1) * nt1 + z1 * hreg[mi][jj][1];
                hreg[mi][jj][0] = h0;
                hreg[mi][jj][1] = h1;

                __half hh0 = __float2half_rn(h0);
                __half hh1 = __float2half_rn(h1);
                uint32_t ph = (uint32_t)__half_as_ushort(hh0) | ((uint32_t)__half_as_ushort(hh1) << 16);
                int kt = j >> 6, cc = j & 63;
                uint32_t off = SW128((uint32_t)(mloc * 128 + cc * 2));
                *(uint32_t*)((char*)&g_hT[wr][mt][kt][0] + off) = ph;

                vp = fmaf(wvv[jj].x, h0, vp);
                vp = fmaf(wvv[jj].y, h1, vp);
            }
            vp += __shfl_xor_sync(0xffffffffu, vp, 1);
            vp += __shfl_xor_sync(0xffffffffu, vp, 2);
            if (ct == 0) {
                int bs = m_g >> 3, a = m_g & 7;
                atomicAdd(&out[((size_t)bs * T_LEN + t) * 8 + a], vp);
            }
        }

        // ---------------- per-mt grid barrier (16 arrivals) ----------------
        if (t < T_LEN - 1) {
            __threadfence();
            __syncthreads();
            if (tid == 0) {
                atomicAdd(&g_arrm[mt][t], 1u);
                while (((volatile unsigned*)g_arrm[mt])[t] < 16u) { }
                __threadfence();
                issueH(t + 1, 0);
                issueH(t + 1, 1);
            }
            __syncthreads();
        }
    }
}

// ---------------------------------------------------------------------------
extern "C" void kernel_launch(void* const* d_in, const int* in_sizes, int n_in,
                              void* d_out, int out_size)
{
    const float* obs  = (const float*)d_in[0];
    const float* W1   = (const float*)d_in[1];
    const float* b1   = (const float*)d_in[2];
    const float* W_ih = (const float*)d_in[3];
    const float* b_ih = (const float*)d_in[4];
    const float* W_hh = (const float*)d_in[5];
    const float* b_hh = (const float*)d_in[6];
    const float* Wv   = (const float*)d_in[7];
    const float* bv   = (const float*)d_in[8];
    float* out = (float*)d_out;

    cudaFuncSetAttribute(gemm1_kernel,       cudaFuncAttributeMaxDynamicSharedMemorySize, 66560);
    cudaFuncSetAttribute(gru_persist_kernel, cudaFuncAttributeMaxDynamicSharedMemorySize, 230400);

    init_kernel<<<2048, 256>>>(out, bv);
    obs_conv_kernel<<<32768, 256>>>(obs);
    prep_kernel<<<3072, 256>>>(W_ih, W_hh, W1);
    gemm1_kernel<<<dim3(4, 1024), 256, 66560>>>(b1);
    gru_persist_kernel<<<dim3(16, 8), 256, 230400>>>(b_hh, b_ih, Wv, out);
}